// round 12
// baseline (speedup 1.0000x reference)
#include <cuda_runtime.h>
#include <cuda_bf16.h>
#include <cstdint>
#include <cstddef>

// ---------------------------------------------------------------------------
// Transformer-XL relative attention — all matmuls via mma.sync m16n8k16 bf16
// (hi/lo split, fp32 accum). tcgen05 unavailable (harness targets plain sm_103).
//
// rel_shift identity: for j <= i + 1024,
//   shift(BD)[b,i,j,n] = (q + r_r_bias) . rk[j - i + 1023, n, :]
//
// R11: attn -> 512 threads / 16 warps (4x4 warp grid), halved per-warp
//      accumulator state (no spills), ldsm4.trans for V. Same math.
// ---------------------------------------------------------------------------

constexpr int BSZ = 4, QLEN = 1024, KLEN = 2048, NH = 16, DH = 64, DM = 1024;

// ---- bf16 split global scratch --------------------------------------------
__device__ __nv_bfloat16 g_w_hi [(size_t)BSZ * KLEN * DM];
__device__ __nv_bfloat16 g_w_lo [(size_t)BSZ * KLEN * DM];
__device__ __nv_bfloat16 g_r_hi [(size_t)KLEN * DM];
__device__ __nv_bfloat16 g_r_lo [(size_t)KLEN * DM];
__device__ __nv_bfloat16 g_wqt_hi [(size_t)DM * DM],     g_wqt_lo [(size_t)DM * DM];
__device__ __nv_bfloat16 g_wkvt_hi[(size_t)2 * DM * DM], g_wkvt_lo[(size_t)2 * DM * DM];
__device__ __nv_bfloat16 g_wrt_hi [(size_t)DM * DM],     g_wrt_lo [(size_t)DM * DM];
__device__ __nv_bfloat16 g_wot_hi [(size_t)DM * DM],     g_wot_lo [(size_t)DM * DM];
__device__ __nv_bfloat16 g_qw_hi[(size_t)BSZ * NH * QLEN * DH], g_qw_lo[(size_t)BSZ * NH * QLEN * DH];
__device__ __nv_bfloat16 g_qr_hi[(size_t)BSZ * NH * QLEN * DH], g_qr_lo[(size_t)BSZ * NH * QLEN * DH];
__device__ __nv_bfloat16 g_k_hi [(size_t)BSZ * NH * KLEN * DH], g_k_lo [(size_t)BSZ * NH * KLEN * DH];
__device__ __nv_bfloat16 g_v_hi [(size_t)BSZ * NH * KLEN * DH], g_v_lo [(size_t)BSZ * NH * KLEN * DH];
__device__ __nv_bfloat16 g_rk_hi[(size_t)NH * KLEN * DH],       g_rk_lo[(size_t)NH * KLEN * DH];
__device__ __nv_bfloat16 g_av_hi[(size_t)BSZ * QLEN * DM], g_av_lo[(size_t)BSZ * QLEN * DM];

// ---------------------------------------------------------------------------
// helpers
// ---------------------------------------------------------------------------
__device__ __forceinline__ uint32_t smem_to_u32(const void* p) {
    uint32_t a;
    asm("{ .reg .u64 t; cvta.to.shared.u64 t, %1; cvt.u32.u64 %0, t; }"
        : "=r"(a) : "l"(p));
    return a;
}
__device__ __forceinline__ uint32_t swz(uint32_t x) { return x ^ ((x >> 3) & 0x70); }

__device__ __forceinline__ void ldsm4(uint32_t* r, uint32_t a) {
    asm volatile("ldmatrix.sync.aligned.m8n8.x4.shared.b16 {%0,%1,%2,%3}, [%4];"
                 : "=r"(r[0]), "=r"(r[1]), "=r"(r[2]), "=r"(r[3]) : "r"(a));
}
__device__ __forceinline__ void ldsm2(uint32_t* r, uint32_t a) {
    asm volatile("ldmatrix.sync.aligned.m8n8.x2.shared.b16 {%0,%1}, [%2];"
                 : "=r"(r[0]), "=r"(r[1]) : "r"(a));
}
__device__ __forceinline__ void ldsm4t(uint32_t* r, uint32_t a) {
    asm volatile("ldmatrix.sync.aligned.m8n8.x4.trans.shared.b16 {%0,%1,%2,%3}, [%4];"
                 : "=r"(r[0]), "=r"(r[1]), "=r"(r[2]), "=r"(r[3]) : "r"(a));
}
__device__ __forceinline__ void mma16816(float* d, const uint32_t* a, const uint32_t* b) {
    asm volatile("mma.sync.aligned.m16n8k16.row.col.f32.bf16.bf16.f32 "
                 "{%0,%1,%2,%3}, {%4,%5,%6,%7}, {%8,%9}, {%0,%1,%2,%3};"
                 : "+f"(d[0]), "+f"(d[1]), "+f"(d[2]), "+f"(d[3])
                 : "r"(a[0]), "r"(a[1]), "r"(a[2]), "r"(a[3]),
                   "r"(b[0]), "r"(b[1]));
}
#define CP16(sm, gm) \
    asm volatile("cp.async.cg.shared.global [%0], [%1], 16;" :: "r"(sm), "l"(gm))
#define CP_COMMIT() asm volatile("cp.async.commit_group;" ::: "memory")
#define CP_WAIT1()  asm volatile("cp.async.wait_group 1;" ::: "memory")
#define CP_WAIT0()  asm volatile("cp.async.wait_group 0;" ::: "memory")

__device__ __forceinline__ void store_split2(__nv_bfloat16* hi, __nv_bfloat16* lo,
                                             size_t off, float x, float y) {
    __nv_bfloat16 hx = __float2bfloat16(x), hy = __float2bfloat16(y);
    __nv_bfloat16 lx = __float2bfloat16(x - __bfloat162float(hx));
    __nv_bfloat16 ly = __float2bfloat16(y - __bfloat162float(hy));
    __nv_bfloat162 h2; h2.x = hx; h2.y = hy;
    __nv_bfloat162 l2; l2.x = lx; l2.y = ly;
    *(__nv_bfloat162*)(hi + off) = h2;
    *(__nv_bfloat162*)(lo + off) = l2;
}

// ---------------------------------------------------------------------------
// Pre-pass 1 (merged): fp32 -> bf16 hi/lo split for w and r.
// ---------------------------------------------------------------------------
constexpr size_t W_UNITS = (size_t)BSZ * KLEN * DM / 4;
constexpr size_t R_UNITS = (size_t)KLEN * DM / 4;

__global__ void convert_all(const float* __restrict__ w, const float* __restrict__ r) {
    size_t u = (size_t)blockIdx.x * blockDim.x + threadIdx.x;
    const float* s;
    __nv_bfloat16 *hi, *lo;
    size_t base;
    if (u < W_UNITS) { s = w; hi = g_w_hi; lo = g_w_lo; base = u; }
    else             { s = r; hi = g_r_hi; lo = g_r_lo; base = u - W_UNITS; }
    size_t i = base * 4;
    float4 v = *(const float4*)(s + i);
    float vv[4] = {v.x, v.y, v.z, v.w};
    __nv_bfloat16 h[4], l[4];
#pragma unroll
    for (int j = 0; j < 4; j++) {
        h[j] = __float2bfloat16(vv[j]);
        l[j] = __float2bfloat16(vv[j] - __bfloat162float(h[j]));
    }
    *(uint2*)(hi + i) = *(uint2*)h;
    *(uint2*)(lo + i) = *(uint2*)l;
}

// ---------------------------------------------------------------------------
// Pre-pass 2 (merged): all 4 weight transposes. W [K][N] fp32 -> [N][K] bf16.
// ---------------------------------------------------------------------------
__global__ void transpose_all(const float* __restrict__ Wq, const float* __restrict__ Wkv,
                              const float* __restrict__ Wr, const float* __restrict__ Wo) {
    __shared__ float t[32][33];
    int idx = blockIdx.x;
    const float* W;
    __nv_bfloat16 *hi, *lo;
    int N, n0, k0;
    if (idx < 1024) {
        W = Wq; hi = g_wqt_hi; lo = g_wqt_lo; N = DM;
        n0 = (idx & 31) * 32; k0 = (idx >> 5) * 32;
    } else if (idx < 3072) {
        int lidx = idx - 1024;
        W = Wkv; hi = g_wkvt_hi; lo = g_wkvt_lo; N = 2 * DM;
        n0 = (lidx & 63) * 32; k0 = (lidx >> 6) * 32;
    } else if (idx < 4096) {
        int lidx = idx - 3072;
        W = Wr; hi = g_wrt_hi; lo = g_wrt_lo; N = DM;
        n0 = (lidx & 31) * 32; k0 = (lidx >> 5) * 32;
    } else {
        int lidx = idx - 4096;
        W = Wo; hi = g_wot_hi; lo = g_wot_lo; N = DM;
        n0 = (lidx & 31) * 32; k0 = (lidx >> 5) * 32;
    }
    int tx = threadIdx.x, ty = threadIdx.y;
#pragma unroll
    for (int i = 0; i < 4; i++)
        t[ty + 8 * i][tx] = W[(size_t)(k0 + ty + 8 * i) * N + n0 + tx];
    __syncthreads();
#pragma unroll
    for (int i = 0; i < 4; i++) {
        float v = t[tx][ty + 8 * i];
        __nv_bfloat16 h = __float2bfloat16(v);
        __nv_bfloat16 l = __float2bfloat16(v - __bfloat162float(h));
        size_t o = (size_t)(n0 + ty + 8 * i) * DM + k0 + tx;
        hi[o] = h;
        lo[o] = l;
    }
}

// ---------------------------------------------------------------------------
// HMMA split-bf16 GEMM body (unchanged from R8). 128x128 tile, 8 warps,
// single 73.7KB buffer -> 2 CTAs/SM.
// ---------------------------------------------------------------------------
constexpr int GEMM_SMEM = 73728;

__device__ __forceinline__ void hgemm_body(
    int mode, int m0, int n0,
    const __nv_bfloat16* __restrict__ Ah, const __nv_bfloat16* __restrict__ Al,
    const __nv_bfloat16* __restrict__ Bh, const __nv_bfloat16* __restrict__ Bl,
    const float* __restrict__ rwb, const float* __restrict__ rrb,
    float* __restrict__ C, char* smc)
{
    const uint32_t sb = smem_to_u32(smc);
    const int tid = threadIdx.x, lane = tid & 31, wid = tid >> 5;
    const int wm = wid >> 1, wn = wid & 1;

    float acc[2][8][4];
#pragma unroll
    for (int a = 0; a < 2; a++)
#pragma unroll
        for (int b = 0; b < 8; b++)
#pragma unroll
            for (int c = 0; c < 4; c++) acc[a][b][c] = 0.f;

#pragma unroll 1
    for (int c = 0; c < 16; c++) {
        const int k0 = c * 64;
#pragma unroll
        for (int it = 0; it < 4; it++) {
            int u = tid + it * 256;
            int row = u >> 3, kk = (u & 7) * 8;
            uint32_t so = row * 144 + kk * 2;
            int am = m0 + row;
            int grow = (mode == 0) ? (((am >> 10) << 11) + QLEN + (am & (QLEN - 1))) : am;
            size_t ao = (size_t)grow * DM + k0 + kk;
            size_t bo = (size_t)(n0 + row) * DM + k0 + kk;
            CP16(sb + so,         Ah + ao);
            CP16(sb + 18432 + so, Al + ao);
            CP16(sb + 36864 + so, Bh + bo);
            CP16(sb + 55296 + so, Bl + bo);
        }
        CP_COMMIT();
        CP_WAIT0();
        __syncthreads();
        const uint32_t aBase = sb + (wm * 32 + (lane & 15)) * 144 + ((lane >> 4) * 8) * 2;
        const uint32_t bBase = sb + 36864 + (wn * 64 + (lane & 7)) * 144
                             + (((lane >> 3) & 1) * 8) * 2;
#pragma unroll
        for (int kk = 0; kk < 4; kk++) {
            uint32_t ah[2][4], al[2][4];
#pragma unroll
            for (int ms = 0; ms < 2; ms++) {
                uint32_t aa = aBase + ms * 16 * 144 + kk * 32;
                ldsm4(ah[ms], aa);
                ldsm4(al[ms], aa + 18432);
            }
#pragma unroll
            for (int ns = 0; ns < 8; ns++) {
                uint32_t ba = bBase + ns * 8 * 144 + kk * 32;
                uint32_t bh2[2], bl2[2];
                ldsm2(bh2, ba);
                ldsm2(bl2, ba + 18432);
                mma16816(acc[0][ns], ah[0], bh2);
                mma16816(acc[1][ns], ah[1], bh2);
                mma16816(acc[0][ns], ah[0], bl2);
                mma16816(acc[1][ns], ah[1], bl2);
                mma16816(acc[0][ns], al[0], bh2);
                mma16816(acc[1][ns], al[1], bh2);
            }
        }
        __syncthreads();
    }

    // epilogue
#pragma unroll
    for (int ms = 0; ms < 2; ms++) {
        int r0 = m0 + wm * 32 + ms * 16 + (lane >> 2);
#pragma unroll
        for (int ns = 0; ns < 8; ns++) {
            int col = n0 + wn * 64 + ns * 8 + (lane & 3) * 2;
#pragma unroll
            for (int h = 0; h < 2; h++) {
                int row = r0 + h * 8;
                float x = acc[ms][ns][h * 2 + 0];
                float y = acc[ms][ns][h * 2 + 1];
                if (mode == 0) {
                    int bb = row >> 10, ii = row & 1023;
                    int head = col >> 6, d = col & 63;
                    size_t off = (((size_t)(bb * NH + head)) * QLEN + ii) * DH + d;
                    store_split2(g_qw_hi, g_qw_lo, off, x + rwb[col], y + rwb[col + 1]);
                    store_split2(g_qr_hi, g_qr_lo, off, x + rrb[col], y + rrb[col + 1]);
                } else if (mode == 1) {
                    int bb = row >> 11, jj = row & 2047;
                    int cc = (col < DM) ? col : col - DM;
                    int head = cc >> 6, d = cc & 63;
                    size_t off = (((size_t)(bb * NH + head)) * KLEN + jj) * DH + d;
                    if (col < DM) store_split2(g_k_hi, g_k_lo, off, x, y);
                    else          store_split2(g_v_hi, g_v_lo, off, x, y);
                } else if (mode == 2) {
                    int head = col >> 6, d = col & 63;
                    size_t off = ((size_t)head * KLEN + row) * DH + d;
                    store_split2(g_rk_hi, g_rk_lo, off, x, y);
                } else {
                    *(float2*)(C + (size_t)row * DM + col) = make_float2(x, y);
                }
            }
        }
    }
}

__global__ void __launch_bounds__(256, 2)
hgemm_proj(const float* __restrict__ rwb, const float* __restrict__ rrb)
{
    extern __shared__ __align__(1024) char smc[];
    int idx = blockIdx.x;
    int mode, m0, n0;
    const __nv_bfloat16 *Ah, *Al, *Bh, *Bl;
    if (idx < 1024) {        // KV: grid 16 x 64
        mode = 1; n0 = (idx & 15) * 128; m0 = (idx >> 4) * 128;
        Ah = g_w_hi; Al = g_w_lo; Bh = g_wkvt_hi; Bl = g_wkvt_lo;
    } else if (idx < 1280) { // Q: grid 8 x 32
        int r = idx - 1024;
        mode = 0; n0 = (r & 7) * 128; m0 = (r >> 3) * 128;
        Ah = g_w_hi; Al = g_w_lo; Bh = g_wqt_hi; Bl = g_wqt_lo;
    } else {                 // R: grid 8 x 16
        int r = idx - 1280;
        mode = 2; n0 = (r & 7) * 128; m0 = (r >> 3) * 128;
        Ah = g_r_hi; Al = g_r_lo; Bh = g_wrt_hi; Bl = g_wrt_lo;
    }
    hgemm_body(mode, m0, n0, Ah, Al, Bh, Bl, rwb, rrb, nullptr, smc);
}

__global__ void __launch_bounds__(256, 2)
hgemm_out(float* __restrict__ C)
{
    extern __shared__ __align__(1024) char smc[];
    hgemm_body(3, blockIdx.y * 128, blockIdx.x * 128,
               g_av_hi, g_av_lo, g_wot_hi, g_wot_lo, nullptr, nullptr, C, smc);
}

// ---------------------------------------------------------------------------
// HMMA flash attention, BI=64 x BJ=128, 512 threads / 16 warps (4x4 grid).
// Warp tile: S 16x32, T 16x48, O 16x16. Region-phased cp.async as in R8.
// ---------------------------------------------------------------------------
constexpr int oKH = 0, oKL = 16384, oVH = 32768, oVL = 49152;   // 128 x 128B
constexpr int oRWH = 65536, oRWL = 90112;                       // 192 x 128B
constexpr int sQWH = 114688, sQWL = 122880, sQRH = 131072, sQRL = 139264; // 64x128B
constexpr int sS = 147456;      // 64 x 132 f32; col 128 = CO, col 129 = LS
constexpr int sPH = 181248, sPL = 198656;  // 64 x 136 bf16 (272B rows)
constexpr int ATTN_SMEM = 216064;

__global__ void __launch_bounds__(512, 1) attn4()
{
    extern __shared__ __align__(1024) char smc[];
    const uint32_t sb = smem_to_u32(smc);
    const int tid = threadIdx.x, lane = tid & 31, wid = tid >> 5;
    const int wm = wid >> 2, wn = wid & 3;
    const int itile = 15 - (blockIdx.x & 15);  // heavy tiles first
    const int bh = blockIdx.x >> 4;
    const int head = bh & 15, bb = bh >> 4;
    const int i0 = itile * 64;
    const int ntiles = (i0 + 1215) >> 7;       // ceil((i0+63+1024+1)/128)

    auto issue_krw = [&](int t) {
        const int j0 = t * 128;
#pragma unroll
        for (int it = 0; it < 2; it++) {       // K: 128 rows x 8 granules
            int u = tid + it * 512;
            int row = u >> 3, g = u & 7;
            uint32_t so = swz((uint32_t)(row * 128 + g * 16));
            size_t off = ((size_t)bh * KLEN + j0 + row) * DH + g * 8;
            CP16(sb + oKH + so, g_k_hi + off);
            CP16(sb + oKL + so, g_k_lo + off);
        }
        const int dbase = j0 - i0 + 960;
#pragma unroll
        for (int it = 0; it < 3; it++) {       // RW: 192 rows x 8 granules
            int u = tid + it * 512;
            int row = u >> 3, g = u & 7;
            int dr = dbase + row;
            dr = dr < 0 ? 0 : (dr > KLEN - 1 ? KLEN - 1 : dr);  // OOB masked later
            uint32_t so = swz((uint32_t)(row * 128 + g * 16));
            size_t off = ((size_t)head * KLEN + dr) * DH + g * 8;
            CP16(sb + oRWH + so, g_rk_hi + off);
            CP16(sb + oRWL + so, g_rk_lo + off);
        }
        CP_COMMIT();
    };
    auto issue_v = [&](int t) {
        const int j0 = t * 128;
#pragma unroll
        for (int it = 0; it < 2; it++) {
            int u = tid + it * 512;
            int row = u >> 3, g = u & 7;
            uint32_t so = swz((uint32_t)(row * 128 + g * 16));
            size_t off = ((size_t)bh * KLEN + j0 + row) * DH + g * 8;
            CP16(sb + oVH + so, g_v_hi + off);
            CP16(sb + oVL + so, g_v_lo + off);
        }
        CP_COMMIT();
    };

    // prologue: KRW(0) [group], Q + V(0) [group], wait all
    issue_krw(0);
    {
        int row = tid >> 3, g = tid & 7;       // 512 = 64 rows x 8 granules
        uint32_t so = swz((uint32_t)(row * 128 + g * 16));
        size_t off = ((size_t)bh * QLEN + i0 + row) * DH + g * 8;
        CP16(sb + sQWH + so, g_qw_hi + off);
        CP16(sb + sQWL + so, g_qw_lo + off);
        CP16(sb + sQRH + so, g_qr_hi + off);
        CP16(sb + sQRL + so, g_qr_lo + off);
    }
    issue_v(0);
    CP_WAIT0();
    __syncthreads();

    float o[2][4];
#pragma unroll
    for (int a = 0; a < 2; a++)
#pragma unroll
        for (int b = 0; b < 4; b++) o[a][b] = 0.f;
    float mrow = -3.0e38f, lrow = 0.f;
    const int srow = tid >> 3, sc0 = (tid & 7) * 16;
    float* Sf = (float*)(smc + sS);

#pragma unroll 1
    for (int t = 0; t < ntiles; t++) {
        const int j0 = t * 128;
        if (t > 0) { CP_WAIT1(); }   // completes KRW(t); V(t) may still fly
        __syncthreads();

        // ---- phase A: S = Qw@K^T (16x32/warp), T = Qr@Rw^T (16x48/warp) ----
        float sacc[4][4], tacc[6][4];
#pragma unroll
        for (int a = 0; a < 4; a++)
#pragma unroll
            for (int b = 0; b < 4; b++) sacc[a][b] = 0.f;
#pragma unroll
        for (int a = 0; a < 6; a++)
#pragma unroll
            for (int b = 0; b < 4; b++) tacc[a][b] = 0.f;
        {
            const int qrow = wm * 16 + (lane & 15);
            const int qg = lane >> 4;
            const int brow = (lane & 7) + ((lane >> 4) << 3);
            const int bg = (lane >> 3) & 1;
#pragma unroll
            for (int kk = 0; kk < 4; kk++) {
                uint32_t qo = swz((uint32_t)(qrow * 128 + qg * 16 + kk * 32));
                uint32_t qwh[4], qwl[4], qrh[4], qrl[4];
                ldsm4(qwh, sb + sQWH + qo);
                ldsm4(qwl, sb + sQWL + qo);
                ldsm4(qrh, sb + sQRH + qo);
                ldsm4(qrl, sb + sQRL + qo);
#pragma unroll
                for (int np = 0; np < 2; np++) {   // K pairs: cols wn*32+np*16
                    uint32_t ko = swz((uint32_t)((wn * 32 + np * 16 + brow) * 128
                                                 + bg * 16 + kk * 32));
                    uint32_t bh4[4], bl4[4];
                    ldsm4(bh4, sb + oKH + ko);
                    ldsm4(bl4, sb + oKL + ko);
                    mma16816(sacc[2 * np],     qwh, bh4);
                    mma16816(sacc[2 * np + 1], qwh, bh4 + 2);
                    mma16816(sacc[2 * np],     qwh, bl4);
                    mma16816(sacc[2 * np + 1], qwh, bl4 + 2);
                    mma16816(sacc[2 * np],     qwl, bh4);
                    mma16816(sacc[2 * np + 1], qwl, bh4 + 2);
                }
#pragma unroll
                for (int np = 0; np < 3; np++) {   // RW pairs: cols wn*48+np*16
                    uint32_t ro = swz((uint32_t)((wn * 48 + np * 16 + brow) * 128
                                                 + bg * 16 + kk * 32));
                    uint32_t bh4[4], bl4[4];
                    ldsm4(bh4, sb + oRWH + ro);
                    ldsm4(bl4, sb + oRWL + ro);
                    mma16816(tacc[2 * np],     qrh, bh4);
                    mma16816(tacc[2 * np + 1], qrh, bh4 + 2);
                    mma16816(tacc[2 * np],     qrh, bl4);
                    mma16816(tacc[2 * np + 1], qrh, bl4 + 2);
                    mma16816(tacc[2 * np],     qrl, bh4);
                    mma16816(tacc[2 * np + 1], qrl, bh4 + 2);
                }
            }
        }
        // write S fragments
        {
            int r0 = wm * 16 + (lane >> 2);
#pragma unroll
            for (int ns = 0; ns < 4; ns++) {
                int c = wn * 32 + ns * 8 + (lane & 3) * 2;
                *(float2*)&Sf[r0 * 132 + c]       = make_float2(sacc[ns][0], sacc[ns][1]);
                *(float2*)&Sf[(r0 + 8) * 132 + c] = make_float2(sacc[ns][2], sacc[ns][3]);
            }
        }
        __syncthreads();

        // ---- phase B: scatter-add T frags into S at c = c' + r - 63 ----
        {
            int r0 = wm * 16 + (lane >> 2);
            int cb = wn * 48 + (lane & 3) * 2 - 63;
#pragma unroll
            for (int ns = 0; ns < 6; ns++) {
#pragma unroll
                for (int h = 0; h < 2; h++) {
                    int r = r0 + h * 8;
                    int c0 = cb + ns * 8 + r;
                    if (c0 >= 0 && c0 < 128) Sf[r * 132 + c0] += tacc[ns][h * 2 + 0];
                    int c1 = c0 + 1;
                    if (c1 >= 0 && c1 < 128) Sf[r * 132 + c1] += tacc[ns][h * 2 + 1];
                }
            }
        }
        __syncthreads();
        if (t + 1 < ntiles) issue_krw(t + 1);  // K/RW regions dead -> prefetch

        // ---- phase C: softmax (8 threads per row, 16 cols each) ----
        {
            const int gi = i0 + srow;
            float sv[16];
            float mt = -3.0e38f;
#pragma unroll
            for (int c2 = 0; c2 < 16; c2++) {
                int c = sc0 + c2;
                float s = Sf[srow * 132 + c] * 0.125f;
                s = ((j0 + c) > gi + 1024) ? -1.0e30f : s;
                sv[c2] = s;
                mt = fmaxf(mt, s);
            }
            mt = fmaxf(mt, __shfl_xor_sync(0xffffffffu, mt, 1));
            mt = fmaxf(mt, __shfl_xor_sync(0xffffffffu, mt, 2));
            mt = fmaxf(mt, __shfl_xor_sync(0xffffffffu, mt, 4));
            float mn = fmaxf(mrow, mt);
            float co = __expf(mrow - mn);
            mrow = mn;
            float rs = 0.f;
            __nv_bfloat16* Ph = (__nv_bfloat16*)(smc + sPH);
            __nv_bfloat16* Pl = (__nv_bfloat16*)(smc + sPL);
#pragma unroll
            for (int c2 = 0; c2 < 16; c2 += 2) {
                float p0 = __expf(sv[c2] - mn);
                float p1 = __expf(sv[c2 + 1] - mn);
                rs += p0 + p1;
                __nv_bfloat16 h0 = __float2bfloat16(p0), h1 = __float2bfloat16(p1);
                __nv_bfloat162 h2; h2.x = h0; h2.y = h1;
                __nv_bfloat162 l2;
                l2.x = __float2bfloat16(p0 - __bfloat162float(h0));
                l2.y = __float2bfloat16(p1 - __bfloat162float(h1));
                int c = sc0 + c2;
                *(__nv_bfloat162*)&Ph[srow * 136 + c] = h2;
                *(__nv_bfloat162*)&Pl[srow * 136 + c] = l2;
            }
            rs += __shfl_xor_sync(0xffffffffu, rs, 1);
            rs += __shfl_xor_sync(0xffffffffu, rs, 2);
            rs += __shfl_xor_sync(0xffffffffu, rs, 4);
            lrow = lrow * co + rs;
            if ((tid & 7) == 0) Sf[srow * 132 + 128] = co;
        }
        if (t + 1 < ntiles) { CP_WAIT1(); } else { CP_WAIT0(); }  // completes V(t)
        __syncthreads();

        // ---- phase D: O (16x16/warp) = O*co + P @ V ----
        {
            float co0 = Sf[(wm * 16 + (lane >> 2)) * 132 + 128];
            float co1 = Sf[(wm * 16 + (lane >> 2) + 8) * 132 + 128];
#pragma unroll
            for (int ns = 0; ns < 2; ns++) {
                o[ns][0] *= co0; o[ns][1] *= co0;
                o[ns][2] *= co1; o[ns][3] *= co1;
            }
            const uint32_t pb = sb + sPH + (wm * 16 + (lane & 15)) * 272
                              + (lane >> 4) * 16;
#pragma unroll
            for (int kk = 0; kk < 8; kk++) {
                uint32_t pah[4], pal[4];
                ldsm4(pah, pb + kk * 32);
                ldsm4(pal, pb + 17408 + kk * 32);
                uint32_t vo = swz((uint32_t)((kk * 16 + (lane & 15)) * 128
                                             + (wn * 16 + (lane >> 4) * 8) * 2));
                uint32_t vh4[4], vl4[4];
                ldsm4t(vh4, sb + oVH + vo);
                ldsm4t(vl4, sb + oVL + vo);
                mma16816(o[0], pah, vh4);
                mma16816(o[1], pah, vh4 + 2);
                mma16816(o[0], pah, vl4);
                mma16816(o[1], pah, vl4 + 2);
                mma16816(o[0], pal, vh4);
                mma16816(o[1], pal, vh4 + 2);
            }
        }
        __syncthreads();                       // V & P fully consumed
        if (t + 1 < ntiles) issue_v(t + 1);
    }

    // ---- finalize: O / l, split to bf16, write [b, i, head*64+d] ----
    if ((tid & 7) == 0) Sf[srow * 132 + 129] = lrow;
    __syncthreads();
    {
        float li0 = 1.f / Sf[(wm * 16 + (lane >> 2)) * 132 + 129];
        float li1 = 1.f / Sf[(wm * 16 + (lane >> 2) + 8) * 132 + 129];
        int gi0 = i0 + wm * 16 + (lane >> 2);
#pragma unroll
        for (int ns = 0; ns < 2; ns++) {
            int d = wn * 16 + ns * 8 + (lane & 3) * 2;
            size_t off0 = ((size_t)bb * QLEN + gi0) * DM + head * DH + d;
            store_split2(g_av_hi, g_av_lo, off0, o[ns][0] * li0, o[ns][1] * li0);
            store_split2(g_av_hi, g_av_lo, off0 + 8 * DM, o[ns][2] * li1, o[ns][3] * li1);
        }
    }
}

// ---------------------------------------------------------------------------
extern "C" void kernel_launch(void* const* d_in, const int* in_sizes, int n_in,
                              void* d_out, int out_size)
{
    const float* w   = (const float*)d_in[0];
    const float* r   = (const float*)d_in[1];
    const float* rwb = (const float*)d_in[2];
    const float* rrb = (const float*)d_in[3];
    const float* Wq  = (const float*)d_in[4];
    const float* Wkv = (const float*)d_in[5];
    const float* Wr  = (const float*)d_in[6];
    const float* Wo  = (const float*)d_in[7];
    float* out = (float*)d_out;

    // merged pre-passes
    convert_all<<<(int)((W_UNITS + R_UNITS) / 256), 256>>>(w, r);
    transpose_all<<<5120, dim3(32, 8)>>>(Wq, Wkv, Wr, Wo);

    cudaFuncSetAttribute(hgemm_proj, cudaFuncAttributeMaxDynamicSharedMemorySize, GEMM_SMEM);
    cudaFuncSetAttribute(hgemm_out,  cudaFuncAttributeMaxDynamicSharedMemorySize, GEMM_SMEM);
    cudaFuncSetAttribute(attn4, cudaFuncAttributeMaxDynamicSharedMemorySize, ATTN_SMEM);

    // merged projections: 1024 (KV) + 256 (Q) + 128 (R) CTAs, 2 CTAs/SM
    hgemm_proj<<<1408, 256, GEMM_SMEM>>>(rwb, rrb);

    // fused relative attention (BI=64, BJ=128, 512 threads)
    attn4<<<BSZ * NH * (QLEN / 64), 512, ATTN_SMEM>>>();

    // output projection
    hgemm_out<<<dim3(DM / 128, (BSZ * QLEN) / 128), 256, GEMM_SMEM>>>(out);
}